// round 2
// baseline (speedup 1.0000x reference)
#include <cuda_runtime.h>
#include <cuda_bf16.h>
#include <cstdint>

// ----------------------------------------------------------------------------
// FPQuantLinear: MXFP4 rotate+quant (x and w) then GEMM + bias.
//   x [8192,4096] f32, w [4096,4096] f32, bias [4096] f32, H [32,32] (unused:
//   Sylvester Hadamard == FWHT via shfl.bfly).  out [8192,4096] f32.
//
// NOTE: harness compiles PTX at .target sm_103 (no 'a'), so tcgen05/TMA-tensor
// are unavailable. Use base-ISA: cp.async + ldmatrix + mma.sync bf16 (HMMA).
// ----------------------------------------------------------------------------

#define T_DIM 8192
#define K_DIM 4096
#define N_DIM 4096

// bf16 scratch for quantized operands (FP4-grid * 2^e values are EXACT in bf16)
__device__ __nv_bfloat16 g_xq[(size_t)T_DIM * K_DIM];
__device__ __nv_bfloat16 g_wq[(size_t)N_DIM * K_DIM];

// ============================ helpers ========================================
__device__ __forceinline__ uint32_t smem_u32(const void* p) {
    uint32_t a;
    asm("{ .reg .u64 t; cvta.to.shared.u64 t, %1; cvt.u32.u64 %0, t; }" : "=r"(a) : "l"(p));
    return a;
}

__device__ __forceinline__ void cp16(uint32_t saddr, const void* g) {
    asm volatile("cp.async.cg.shared.global [%0], [%1], 16;" :: "r"(saddr), "l"(g) : "memory");
}
#define CP_COMMIT() asm volatile("cp.async.commit_group;" ::: "memory")
#define CP_WAIT(n)  asm volatile("cp.async.wait_group %0;" :: "n"(n) : "memory")

__device__ __forceinline__ void ldmatrix_x4(uint32_t& r0, uint32_t& r1,
                                            uint32_t& r2, uint32_t& r3, uint32_t addr) {
    asm volatile("ldmatrix.sync.aligned.m8n8.x4.shared.b16 {%0,%1,%2,%3}, [%4];"
                 : "=r"(r0), "=r"(r1), "=r"(r2), "=r"(r3) : "r"(addr));
}

__device__ __forceinline__ void mma_16816(float* d, const uint32_t* a,
                                          const uint32_t* b) {
    asm volatile(
        "mma.sync.aligned.m16n8k16.row.col.f32.bf16.bf16.f32 "
        "{%0,%1,%2,%3}, {%4,%5,%6,%7}, {%8,%9}, {%0,%1,%2,%3};"
        : "+f"(d[0]), "+f"(d[1]), "+f"(d[2]), "+f"(d[3])
        : "r"(a[0]), "r"(a[1]), "r"(a[2]), "r"(a[3]), "r"(b[0]), "r"(b[1]));
}

// ============================ Quant kernel ===================================
// One warp per 32-element group: FWHT (5 bfly stages), amax, E8M0 scale,
// FP4 snap with strict-greater midpoints (matches reference `a > mids`).
__device__ __forceinline__ float exp2i_f(int e) {
    return (e >= -126) ? __uint_as_float((uint32_t)(e + 127) << 23)
                       : __uint_as_float(0x00800000u >> (-126 - e));
}

__global__ void __launch_bounds__(256) quant_kernel(const float* __restrict__ in, int which) {
    __nv_bfloat16* __restrict__ out = which ? g_wq : g_xq;
    const int lane = threadIdx.x & 31;
    const size_t grp = (size_t)blockIdx.x * 8 + (threadIdx.x >> 5);

    float v = in[grp * 32 + lane];

    #pragma unroll
    for (int m = 1; m < 32; m <<= 1) {
        float o = __shfl_xor_sync(0xffffffffu, v, m);
        v = (lane & m) ? (o - v) : (v + o);
    }
    v *= 0.17677669529663688f;  // 2^-2.5 (orthonormal scale)

    float a = fabsf(v);
    #pragma unroll
    for (int m = 16; m; m >>= 1) a = fmaxf(a, __shfl_xor_sync(0xffffffffu, a, m));
    a = fmaxf(a, 1.17549435e-38f);  // 2^-126 floor, as reference

    int e = (int)(__float_as_uint(a) >> 23) - 129;  // floor(log2 a) - 2
    e = max(-127, min(127, e));
    const float scale = exp2i_f(e);
    const float inv   = exp2i_f(-e);

    const float s  = v * inv;
    const float aa = fminf(fabsf(s), 6.0f);
    float g;
    if (aa > 1.75f) g = (aa > 3.5f) ? ((aa > 5.0f) ? 6.f : 4.f)
                                    : ((aa > 2.5f) ? 3.f : 2.f);
    else            g = (aa > 0.75f) ? ((aa > 1.25f) ? 1.5f : 1.f)
                                     : ((aa > 0.25f) ? 0.5f : 0.f);
    const float q = copysignf(g, s) * scale;  // exact in bf16

    out[grp * 32 + lane] = __float2bfloat16(q);
}

// ============================ GEMM kernel ====================================
// C[8192,4096] = Xq * Wq^T + bias.   CTA tile 128x128, K-tile 64 bf16 (128B
// rows, XOR-swizzled), 3-stage cp.async pipeline, 8 warps x (64x32) HMMA.

#define TK       64
#define KTILES   (K_DIM / TK)       // 64
#define STAGES   3
#define STAGE_BYTES 32768u          // A(16KB) + B(16KB)
#define SMEM_BIAS   0u              // 512B
#define SMEM_TILES  1024u
#define GEMM_SMEM_BYTES (SMEM_TILES + STAGES * STAGE_BYTES)  // 99328

__device__ __forceinline__ void load_tiles(uint32_t stage_base, int m0, int n0,
                                           int k0, int tid) {
    const __nv_bfloat16* __restrict__ A = g_xq;
    const __nv_bfloat16* __restrict__ B = g_wq;
    const uint32_t sA = stage_base;
    const uint32_t sB = stage_base + 16384u;
    #pragma unroll
    for (int i = 0; i < 4; i++) {
        int idx = tid + i * 256;            // 0..1023
        int row = idx >> 3;                 // 0..127
        int ch  = idx & 7;                  // 16B chunk in 128B row
        uint32_t off = (uint32_t)row * 128u + (uint32_t)ch * 16u;
        uint32_t sw  = off ^ ((off >> 3) & 0x70u);
        cp16(sA + sw, A + (size_t)(m0 + row) * K_DIM + k0 + ch * 8);
        cp16(sB + sw, B + (size_t)(n0 + row) * K_DIM + k0 + ch * 8);
    }
    CP_COMMIT();
}

__global__ void __launch_bounds__(256) mxfp4_gemm_kernel(const float* __restrict__ bias,
                                                         float* __restrict__ C) {
    extern __shared__ char smem[];
    const uint32_t sb = smem_u32(smem);
    const int tid  = threadIdx.x;
    const int wid  = tid >> 5;
    const int lane = tid & 31;

    const int mt = blockIdx.x & 63;
    const int nt = blockIdx.x >> 6;
    const int m0 = mt * 128;
    const int n0 = nt * 128;

    // warp tile: 2 (m) x 4 (n) warps, each 64x32
    const int wm0 = (wid & 1) * 64;
    const int wn0 = (wid >> 1) * 32;

    if (tid < 128) ((float*)(smem + SMEM_BIAS))[tid] = bias[n0 + tid];

    // prologue: stages 0,1
    load_tiles(sb + SMEM_TILES + 0 * STAGE_BYTES, m0, n0, 0 * TK, tid);
    load_tiles(sb + SMEM_TILES + 1 * STAGE_BYTES, m0, n0, 1 * TK, tid);

    float acc[4][4][4];
    #pragma unroll
    for (int i = 0; i < 4; i++)
        #pragma unroll
        for (int j = 0; j < 4; j++)
            #pragma unroll
            for (int r = 0; r < 4; r++) acc[i][j][r] = 0.0f;

    // precomputed lane pieces for ldmatrix addressing
    const int aRowL = lane & 15;            // A: row within 16-row frag
    const int aColH = (lane >> 4) & 1;      // A: 8-col half
    const int bRowL = lane & 7;             // B: n-row within 8
    const int bSel  = (lane >> 3) & 3;      // B: {k-half, n-frag+1} selector

    for (int kt = 0; kt < KTILES; kt++) {
        const uint32_t cur = sb + SMEM_TILES + (uint32_t)(kt % STAGES) * STAGE_BYTES;
        if (kt == KTILES - 1) { CP_WAIT(0); } else { CP_WAIT(1); }
        __syncthreads();

        const uint32_t sA = cur;
        const uint32_t sB = cur + 16384u;

        #pragma unroll
        for (int ks = 0; ks < 4; ks++) {
            // A fragments: 4 x ldmatrix.x4 (one per 16-row m-frag)
            uint32_t af[4][4];
            #pragma unroll
            for (int mi = 0; mi < 4; mi++) {
                int row  = wm0 + mi * 16 + aRowL;
                int colb = ks * 32 + aColH * 16;
                uint32_t addr = sA + (uint32_t)row * 128u
                              + (uint32_t)(colb ^ ((row & 7) * 16));
                ldmatrix_x4(af[mi][0], af[mi][1], af[mi][2], af[mi][3], addr);
            }
            // B fragments: 2 x ldmatrix.x4 (each covers two 8-col n-frags)
            uint32_t bf[4][2];
            #pragma unroll
            for (int nb = 0; nb < 2; nb++) {
                // lanes 0-7: nfrag 2nb k-half0; 8-15: 2nb k-half1;
                // 16-23: 2nb+1 half0; 24-31: 2nb+1 half1
                int nrow = wn0 + (nb * 2 + (bSel >> 1)) * 8 + bRowL;
                int colb = ks * 32 + (bSel & 1) * 16;
                uint32_t addr = sB + (uint32_t)nrow * 128u
                              + (uint32_t)(colb ^ ((nrow & 7) * 16));
                uint32_t r0, r1, r2, r3;
                ldmatrix_x4(r0, r1, r2, r3, addr);
                bf[nb * 2 + 0][0] = r0; bf[nb * 2 + 0][1] = r1;
                bf[nb * 2 + 1][0] = r2; bf[nb * 2 + 1][1] = r3;
            }
            #pragma unroll
            for (int mi = 0; mi < 4; mi++)
                #pragma unroll
                for (int ni = 0; ni < 4; ni++)
                    mma_16816(acc[mi][ni], af[mi], bf[ni]);
        }

        __syncthreads();
        if (kt + 2 < KTILES) {
            load_tiles(sb + SMEM_TILES + (uint32_t)((kt + 2) % STAGES) * STAGE_BYTES,
                       m0, n0, (kt + 2) * TK, tid);
        }
    }

    // epilogue: add bias, store float2 per (frag, row-half)
    const float* bsm = (const float*)(smem + SMEM_BIAS);
    const int qr = lane >> 2;          // 0..7
    const int qc = (lane & 3) * 2;     // 0,2,4,6
    #pragma unroll
    for (int mi = 0; mi < 4; mi++) {
        #pragma unroll
        for (int ni = 0; ni < 4; ni++) {
            const int col = wn0 + ni * 8 + qc;
            const float b0 = bsm[col], b1 = bsm[col + 1];
            const int r0 = m0 + wm0 + mi * 16 + qr;
            float2 v0 = make_float2(acc[mi][ni][0] + b0, acc[mi][ni][1] + b1);
            float2 v1 = make_float2(acc[mi][ni][2] + b0, acc[mi][ni][3] + b1);
            *reinterpret_cast<float2*>(C + (size_t)r0 * N_DIM + n0 + col) = v0;
            *reinterpret_cast<float2*>(C + (size_t)(r0 + 8) * N_DIM + n0 + col) = v1;
        }
    }
}

// ============================ launch =========================================
extern "C" void kernel_launch(void* const* d_in, const int* in_sizes, int n_in,
                              void* d_out, int out_size) {
    const float* x    = (const float*)d_in[0];
    const float* w    = (const float*)d_in[1];
    const float* bias = (const float*)d_in[2];
    float* out        = (float*)d_out;

    const int xg = (T_DIM * K_DIM) / 32;
    const int wg = (N_DIM * K_DIM) / 32;
    quant_kernel<<<xg / 8, 256>>>(x, 0);
    quant_kernel<<<wg / 8, 256>>>(w, 1);

    cudaFuncSetAttribute(mxfp4_gemm_kernel,
                         cudaFuncAttributeMaxDynamicSharedMemorySize, GEMM_SMEM_BYTES);
    const int grid = (T_DIM / 128) * (N_DIM / 128);  // 2048
    mxfp4_gemm_kernel<<<grid, 256, GEMM_SMEM_BYTES>>>(bias, out);
}

// round 3
// speedup vs baseline: 1.0097x; 1.0097x over previous
#include <cuda_runtime.h>
#include <cuda_bf16.h>
#include <cuda_fp8.h>
#include <cstdint>

// ----------------------------------------------------------------------------
// FPQuantLinear: MXFP4 rotate+quant (x and w) then GEMM + bias.
//   x [8192,4096] f32, w [4096,4096] f32, bias [4096] f32, H (unused: Sylvester
//   Hadamard == FWHT in registers).  out [8192,4096] f32.
//
// .target sm_103 (no 'a') -> no tcgen05/TMA. Path: cp.async + ldmatrix +
// mma.sync m16n8k32 e4m3 (FP4-grid values are EXACT in e4m3 after a fixed
// power-of-2 pre-scale; epilogue multiplies by the inverse).
// ----------------------------------------------------------------------------

#define T_DIM 8192
#define K_DIM 4096
#define N_DIM 4096

// fp8 scratch: x pre-scaled by 2^4, w by 2^8 (exactness in e4m3); epilogue *2^-12
__device__ uint8_t g_xq[(size_t)T_DIM * K_DIM];
__device__ uint8_t g_wq[(size_t)N_DIM * K_DIM];

// ============================ helpers ========================================
__device__ __forceinline__ uint32_t smem_u32(const void* p) {
    uint32_t a;
    asm("{ .reg .u64 t; cvta.to.shared.u64 t, %1; cvt.u32.u64 %0, t; }" : "=r"(a) : "l"(p));
    return a;
}

__device__ __forceinline__ void cp16(uint32_t saddr, const void* g) {
    asm volatile("cp.async.cg.shared.global [%0], [%1], 16;" :: "r"(saddr), "l"(g) : "memory");
}
#define CP_COMMIT() asm volatile("cp.async.commit_group;" ::: "memory")
#define CP_WAIT(n)  asm volatile("cp.async.wait_group %0;" :: "n"(n) : "memory")

__device__ __forceinline__ void ldmatrix_x4(uint32_t& r0, uint32_t& r1,
                                            uint32_t& r2, uint32_t& r3, uint32_t addr) {
    asm volatile("ldmatrix.sync.aligned.m8n8.x4.shared.b16 {%0,%1,%2,%3}, [%4];"
                 : "=r"(r0), "=r"(r1), "=r"(r2), "=r"(r3) : "r"(addr));
}

// fp8 e4m3 MMA, byte-layout-identical to the bf16 fragment addressing
__device__ __forceinline__ void mma_fp8(float* d, const uint32_t* a, const uint32_t* b) {
    asm volatile(
        "mma.sync.aligned.m16n8k32.row.col.f32.e4m3.e4m3.f32 "
        "{%0,%1,%2,%3}, {%4,%5,%6,%7}, {%8,%9}, {%0,%1,%2,%3};"
        : "+f"(d[0]), "+f"(d[1]), "+f"(d[2]), "+f"(d[3])
        : "r"(a[0]), "r"(a[1]), "r"(a[2]), "r"(a[3]), "r"(b[0]), "r"(b[1]));
}

// pack 4 floats -> 4 e4m3 bytes (elem0 in lowest byte)
__device__ __forceinline__ uint32_t pack_e4m3_4(float a, float b, float c, float d) {
    uint16_t lo, hi;
    asm("cvt.rn.satfinite.e4m3x2.f32 %0, %1, %2;" : "=h"(lo) : "f"(b), "f"(a));
    asm("cvt.rn.satfinite.e4m3x2.f32 %0, %1, %2;" : "=h"(hi) : "f"(d), "f"(c));
    return (uint32_t)lo | ((uint32_t)hi << 16);
}

__device__ __forceinline__ float exp2i_f(int e) {
    return (e >= -126) ? __uint_as_float((uint32_t)(e + 127) << 23)
                       : __uint_as_float(0x00800000u >> (-126 - e));
}

// ============================ Quant kernel ===================================
// One THREAD per 32-element group: 8x LDG.128, in-register FWHT (5 stages),
// register amax, E8M0 scale, FP4 snap (strict-greater midpoints, as reference),
// pre-scale by outmul (2^4 for x, 2^8 for w), pack to e4m3, 2x STG.128.
__global__ void __launch_bounds__(256) quant_kernel(const float* __restrict__ in,
                                                    uint8_t* __restrict__ out,
                                                    float outmul) {
    const size_t g = (size_t)blockIdx.x * 256 + threadIdx.x;
    const float4* __restrict__ p = reinterpret_cast<const float4*>(in) + g * 8;

    float v[32];
    #pragma unroll
    for (int j = 0; j < 8; j++) {
        float4 t = p[j];
        v[j * 4 + 0] = t.x; v[j * 4 + 1] = t.y;
        v[j * 4 + 2] = t.z; v[j * 4 + 3] = t.w;
    }

    // FWHT (Sylvester H * 32^-0.5 applied after)
    #pragma unroll
    for (int s = 1; s < 32; s <<= 1) {
        #pragma unroll
        for (int i = 0; i < 32; i++) {
            if (!(i & s)) {
                float a = v[i], b = v[i | s];
                v[i] = a + b; v[i | s] = a - b;
            }
        }
    }
    #pragma unroll
    for (int i = 0; i < 32; i++) v[i] *= 0.17677669529663688f;  // 2^-2.5

    float amax = 0.0f;
    #pragma unroll
    for (int i = 0; i < 32; i++) amax = fmaxf(amax, fabsf(v[i]));
    amax = fmaxf(amax, 1.17549435e-38f);  // 2^-126 floor, as reference

    int e = (int)(__float_as_uint(amax) >> 23) - 129;  // floor(log2 amax) - 2
    e = max(-127, min(127, e));
    const float inv  = exp2i_f(-e);
    const float smul = exp2i_f(e) * outmul;            // exact power-of-2

    float q[32];
    #pragma unroll
    for (int i = 0; i < 32; i++) {
        const float s  = v[i] * inv;
        const float aa = fminf(fabsf(s), 6.0f);
        float gg;
        if (aa > 1.75f) gg = (aa > 3.5f) ? ((aa > 5.0f) ? 6.f : 4.f)
                                         : ((aa > 2.5f) ? 3.f : 2.f);
        else            gg = (aa > 0.75f) ? ((aa > 1.25f) ? 1.5f : 1.f)
                                          : ((aa > 0.25f) ? 0.5f : 0.f);
        q[i] = copysignf(gg, s) * smul;                // exact in e4m3
    }

    uint4 w0, w1;
    w0.x = pack_e4m3_4(q[0],  q[1],  q[2],  q[3]);
    w0.y = pack_e4m3_4(q[4],  q[5],  q[6],  q[7]);
    w0.z = pack_e4m3_4(q[8],  q[9],  q[10], q[11]);
    w0.w = pack_e4m3_4(q[12], q[13], q[14], q[15]);
    w1.x = pack_e4m3_4(q[16], q[17], q[18], q[19]);
    w1.y = pack_e4m3_4(q[20], q[21], q[22], q[23]);
    w1.z = pack_e4m3_4(q[24], q[25], q[26], q[27]);
    w1.w = pack_e4m3_4(q[28], q[29], q[30], q[31]);

    uint4* o = reinterpret_cast<uint4*>(out + g * 32);
    o[0] = w0; o[1] = w1;
}

// ============================ GEMM kernel ====================================
// C = Xq8 * Wq8^T * 2^-12 + bias.  CTA tile 128x128, K-tile 128 fp8 (128B
// swizzled rows), 3-stage cp.async pipeline, 8 warps x (64x32), fp8 HMMA.

#define TK       128
#define KTILES   (K_DIM / TK)       // 32
#define STAGES   3
#define STAGE_BYTES 32768u          // A(16KB) + B(16KB)
#define SMEM_BIAS   0u
#define SMEM_TILES  1024u
#define GEMM_SMEM_BYTES (SMEM_TILES + STAGES * STAGE_BYTES)  // 99328
#define SCALE_OUT 0.000244140625f   // 2^-12

__device__ __forceinline__ void load_tiles(uint32_t stage_base, int m0, int n0,
                                           int k0, int tid) {
    const uint8_t* __restrict__ A = g_xq;
    const uint8_t* __restrict__ B = g_wq;
    const uint32_t sA = stage_base;
    const uint32_t sB = stage_base + 16384u;
    #pragma unroll
    for (int i = 0; i < 4; i++) {
        int idx = tid + i * 256;            // 0..1023
        int row = idx >> 3;                 // 0..127
        int ch  = idx & 7;                  // 16B chunk in 128B row
        uint32_t off = (uint32_t)row * 128u + (uint32_t)ch * 16u;
        uint32_t sw  = off ^ ((off >> 3) & 0x70u);
        cp16(sA + sw, A + (size_t)(m0 + row) * K_DIM + k0 + ch * 16);
        cp16(sB + sw, B + (size_t)(n0 + row) * K_DIM + k0 + ch * 16);
    }
    CP_COMMIT();
}

__global__ void __launch_bounds__(256) mxfp4_gemm_kernel(const float* __restrict__ bias,
                                                         float* __restrict__ C) {
    extern __shared__ char smem[];
    const uint32_t sb = smem_u32(smem);
    const int tid  = threadIdx.x;
    const int wid  = tid >> 5;
    const int lane = tid & 31;

    const int mt = blockIdx.x & 63;
    const int nt = blockIdx.x >> 6;
    const int m0 = mt * 128;
    const int n0 = nt * 128;

    const int wm0 = (wid & 1) * 64;
    const int wn0 = (wid >> 1) * 32;

    if (tid < 128) ((float*)(smem + SMEM_BIAS))[tid] = bias[n0 + tid];

    load_tiles(sb + SMEM_TILES + 0 * STAGE_BYTES, m0, n0, 0 * TK, tid);
    load_tiles(sb + SMEM_TILES + 1 * STAGE_BYTES, m0, n0, 1 * TK, tid);

    float acc[4][4][4];
    #pragma unroll
    for (int i = 0; i < 4; i++)
        #pragma unroll
        for (int j = 0; j < 4; j++)
            #pragma unroll
            for (int r = 0; r < 4; r++) acc[i][j][r] = 0.0f;

    const int aRowL = lane & 15;
    const int aColH = (lane >> 4) & 1;
    const int bRowL = lane & 7;
    const int bSel  = (lane >> 3) & 3;

    for (int kt = 0; kt < KTILES; kt++) {
        const uint32_t cur = sb + SMEM_TILES + (uint32_t)(kt % STAGES) * STAGE_BYTES;
        if (kt == KTILES - 1) { CP_WAIT(0); } else { CP_WAIT(1); }
        __syncthreads();

        const uint32_t sA = cur;
        const uint32_t sB = cur + 16384u;

        #pragma unroll
        for (int ks = 0; ks < 4; ks++) {            // 4 x k32 per 128-elem tile
            uint32_t af[4][4];
            #pragma unroll
            for (int mi = 0; mi < 4; mi++) {
                int row  = wm0 + mi * 16 + aRowL;
                int colb = ks * 32 + aColH * 16;    // byte column
                uint32_t addr = sA + (uint32_t)row * 128u
                              + (uint32_t)(colb ^ ((row & 7) * 16));
                ldmatrix_x4(af[mi][0], af[mi][1], af[mi][2], af[mi][3], addr);
            }
            uint32_t bf[4][2];
            #pragma unroll
            for (int nb = 0; nb < 2; nb++) {
                int nrow = wn0 + (nb * 2 + (bSel >> 1)) * 8 + bRowL;
                int colb = ks * 32 + (bSel & 1) * 16;
                uint32_t addr = sB + (uint32_t)nrow * 128u
                              + (uint32_t)(colb ^ ((nrow & 7) * 16));
                uint32_t r0, r1, r2, r3;
                ldmatrix_x4(r0, r1, r2, r3, addr);
                bf[nb * 2 + 0][0] = r0; bf[nb * 2 + 0][1] = r1;
                bf[nb * 2 + 1][0] = r2; bf[nb * 2 + 1][1] = r3;
            }
            #pragma unroll
            for (int mi = 0; mi < 4; mi++)
                #pragma unroll
                for (int ni = 0; ni < 4; ni++)
                    mma_fp8(acc[mi][ni], af[mi], bf[ni]);
        }

        __syncthreads();
        if (kt + 2 < KTILES) {
            load_tiles(sb + SMEM_TILES + (uint32_t)((kt + 2) % STAGES) * STAGE_BYTES,
                       m0, n0, (kt + 2) * TK, tid);
        }
    }

    // epilogue: out = acc * 2^-12 + bias
    const float* bsm = (const float*)(smem + SMEM_BIAS);
    const int qr = lane >> 2;
    const int qc = (lane & 3) * 2;
    #pragma unroll
    for (int mi = 0; mi < 4; mi++) {
        #pragma unroll
        for (int ni = 0; ni < 4; ni++) {
            const int col = wn0 + ni * 8 + qc;
            const float b0 = bsm[col], b1 = bsm[col + 1];
            const int r0 = m0 + wm0 + mi * 16 + qr;
            float2 v0 = make_float2(fmaf(acc[mi][ni][0], SCALE_OUT, b0),
                                    fmaf(acc[mi][ni][1], SCALE_OUT, b1));
            float2 v1 = make_float2(fmaf(acc[mi][ni][2], SCALE_OUT, b0),
                                    fmaf(acc[mi][ni][3], SCALE_OUT, b1));
            *reinterpret_cast<float2*>(C + (size_t)r0 * N_DIM + n0 + col) = v0;
            *reinterpret_cast<float2*>(C + (size_t)(r0 + 8) * N_DIM + n0 + col) = v1;
        }
    }
}

// ============================ launch =========================================
extern "C" void kernel_launch(void* const* d_in, const int* in_sizes, int n_in,
                              void* d_out, int out_size) {
    const float* x    = (const float*)d_in[0];
    const float* w    = (const float*)d_in[1];
    const float* bias = (const float*)d_in[2];
    float* out        = (float*)d_out;

    uint8_t* xq;
    uint8_t* wq;
    cudaGetSymbolAddress((void**)&xq, g_xq);
    cudaGetSymbolAddress((void**)&wq, g_wq);

    // x groups: 8192*4096/32 = 1,048,576 ; w groups: 524,288
    quant_kernel<<<1048576 / 256, 256>>>(x, xq, 16.0f);   // 2^4 pre-scale
    quant_kernel<<<524288 / 256, 256>>>(w, wq, 256.0f);   // 2^8 pre-scale

    cudaFuncSetAttribute(mxfp4_gemm_kernel,
                         cudaFuncAttributeMaxDynamicSharedMemorySize, GEMM_SMEM_BYTES);
    const int grid = (T_DIM / 128) * (N_DIM / 128);  // 2048
    mxfp4_gemm_kernel<<<grid, 256, GEMM_SMEM_BYTES>>>(bias, out);
}

// round 4
// speedup vs baseline: 1.1876x; 1.1762x over previous
#include <cuda_runtime.h>
#include <cuda_bf16.h>
#include <cstdint>

// ----------------------------------------------------------------------------
// FPQuantLinear: MXFP4 rotate+quant (x and w) then GEMM + bias.
//   x [8192,4096] f32, w [4096,4096] f32, bias [4096] f32, H (unused: Sylvester
//   Hadamard == FWHT in registers).  out [8192,4096] f32.
//
// .target sm_103 (no 'a') -> no tcgen05/TMA. Path: cp.async + ldmatrix +
// mma.sync m16n8k16 bf16 (FP4-grid * 2^e values are EXACT in bf16).
// fp8 mma.sync measured SLOWER on this chip (R3) -> bf16 is the right operand.
// ----------------------------------------------------------------------------

#define T_DIM 8192
#define K_DIM 4096
#define N_DIM 4096

__device__ __nv_bfloat16 g_xq[(size_t)T_DIM * K_DIM];
__device__ __nv_bfloat16 g_wq[(size_t)N_DIM * K_DIM];

// ============================ helpers ========================================
__device__ __forceinline__ uint32_t smem_u32(const void* p) {
    uint32_t a;
    asm("{ .reg .u64 t; cvta.to.shared.u64 t, %1; cvt.u32.u64 %0, t; }" : "=r"(a) : "l"(p));
    return a;
}

__device__ __forceinline__ void cp16(uint32_t saddr, const void* g) {
    asm volatile("cp.async.cg.shared.global [%0], [%1], 16;" :: "r"(saddr), "l"(g) : "memory");
}
#define CP_COMMIT() asm volatile("cp.async.commit_group;" ::: "memory")
#define CP_WAIT(n)  asm volatile("cp.async.wait_group %0;" :: "n"(n) : "memory")

__device__ __forceinline__ void ldmatrix_x4(uint32_t& r0, uint32_t& r1,
                                            uint32_t& r2, uint32_t& r3, uint32_t addr) {
    asm volatile("ldmatrix.sync.aligned.m8n8.x4.shared.b16 {%0,%1,%2,%3}, [%4];"
                 : "=r"(r0), "=r"(r1), "=r"(r2), "=r"(r3) : "r"(addr));
}

__device__ __forceinline__ void mma_16816(float* d, const uint32_t* a, const uint32_t* b) {
    asm volatile(
        "mma.sync.aligned.m16n8k16.row.col.f32.bf16.bf16.f32 "
        "{%0,%1,%2,%3}, {%4,%5,%6,%7}, {%8,%9}, {%0,%1,%2,%3};"
        : "+f"(d[0]), "+f"(d[1]), "+f"(d[2]), "+f"(d[3])
        : "r"(a[0]), "r"(a[1]), "r"(a[2]), "r"(a[3]), "r"(b[0]), "r"(b[1]));
}

__device__ __forceinline__ uint32_t pack_bf16_2(float a, float b) {
    uint32_t r;
    asm("cvt.rn.bf16x2.f32 %0, %1, %2;" : "=r"(r) : "f"(b), "f"(a));
    return r;
}

__device__ __forceinline__ float exp2i_f(int e) {
    return (e >= -126) ? __uint_as_float((uint32_t)(e + 127) << 23)
                       : __uint_as_float(0x00800000u >> (-126 - e));
}

// ============================ Quant kernel ===================================
// One THREAD per 32-group: 8x LDG.128, in-register FWHT, amax, E8M0 scale,
// FP4 snap (strict-greater midpoints, as reference), bf16 pack, 4x STG.128.
__global__ void __launch_bounds__(256) quant_kernel(const float* __restrict__ in,
                                                    __nv_bfloat16* __restrict__ out) {
    const size_t g = (size_t)blockIdx.x * 256 + threadIdx.x;
    const float4* __restrict__ p = reinterpret_cast<const float4*>(in) + g * 8;

    float v[32];
    #pragma unroll
    for (int j = 0; j < 8; j++) {
        float4 t = p[j];
        v[j * 4 + 0] = t.x; v[j * 4 + 1] = t.y;
        v[j * 4 + 2] = t.z; v[j * 4 + 3] = t.w;
    }

    #pragma unroll
    for (int s = 1; s < 32; s <<= 1) {
        #pragma unroll
        for (int i = 0; i < 32; i++) {
            if (!(i & s)) {
                float a = v[i], b = v[i | s];
                v[i] = a + b; v[i | s] = a - b;
            }
        }
    }
    #pragma unroll
    for (int i = 0; i < 32; i++) v[i] *= 0.17677669529663688f;  // 32^-0.5

    float amax = 0.0f;
    #pragma unroll
    for (int i = 0; i < 32; i++) amax = fmaxf(amax, fabsf(v[i]));
    amax = fmaxf(amax, 1.17549435e-38f);  // 2^-126 floor, as reference

    int e = (int)(__float_as_uint(amax) >> 23) - 129;  // floor(log2 amax) - 2
    e = max(-127, min(127, e));
    const float inv   = exp2i_f(-e);
    const float scale = exp2i_f(e);

    float q[32];
    #pragma unroll
    for (int i = 0; i < 32; i++) {
        const float s  = v[i] * inv;
        const float aa = fminf(fabsf(s), 6.0f);
        float gg;
        if (aa > 1.75f) gg = (aa > 3.5f) ? ((aa > 5.0f) ? 6.f : 4.f)
                                         : ((aa > 2.5f) ? 3.f : 2.f);
        else            gg = (aa > 0.75f) ? ((aa > 1.25f) ? 1.5f : 1.f)
                                          : ((aa > 0.25f) ? 0.5f : 0.f);
        q[i] = copysignf(gg, s) * scale;  // exact in bf16
    }

    uint4 w0, w1, w2, w3;
    w0.x = pack_bf16_2(q[0],  q[1]);  w0.y = pack_bf16_2(q[2],  q[3]);
    w0.z = pack_bf16_2(q[4],  q[5]);  w0.w = pack_bf16_2(q[6],  q[7]);
    w1.x = pack_bf16_2(q[8],  q[9]);  w1.y = pack_bf16_2(q[10], q[11]);
    w1.z = pack_bf16_2(q[12], q[13]); w1.w = pack_bf16_2(q[14], q[15]);
    w2.x = pack_bf16_2(q[16], q[17]); w2.y = pack_bf16_2(q[18], q[19]);
    w2.z = pack_bf16_2(q[20], q[21]); w2.w = pack_bf16_2(q[22], q[23]);
    w3.x = pack_bf16_2(q[24], q[25]); w3.y = pack_bf16_2(q[26], q[27]);
    w3.z = pack_bf16_2(q[28], q[29]); w3.w = pack_bf16_2(q[30], q[31]);

    uint4* o = reinterpret_cast<uint4*>(out + g * 32);
    o[0] = w0; o[1] = w1; o[2] = w2; o[3] = w3;
}

// ============================ GEMM kernel ====================================
// C = Xq * Wq^T + bias.  CTA tile 128x128, K-tile 64 bf16 (128B swizzled rows),
// 3-stage cp.async, 8 warps x (64x32) HMMA, 2 CTAs/SM, one barrier per k-tile.

#define TK       64
#define KTILES   (K_DIM / TK)       // 64
#define STAGES   3
#define STAGE_BYTES 32768u          // A(16KB) + B(16KB)
#define SMEM_BIAS   0u
#define SMEM_TILES  1024u
#define GEMM_SMEM_BYTES (SMEM_TILES + STAGES * STAGE_BYTES)  // 99328 (x2 per SM)

__device__ __forceinline__ void load_tiles(uint32_t stage_base, int m0, int n0,
                                           int k0, int tid) {
    const __nv_bfloat16* __restrict__ A = g_xq;
    const __nv_bfloat16* __restrict__ B = g_wq;
    const uint32_t sA = stage_base;
    const uint32_t sB = stage_base + 16384u;
    #pragma unroll
    for (int i = 0; i < 4; i++) {
        int idx = tid + i * 256;            // 0..1023
        int row = idx >> 3;                 // 0..127
        int ch  = idx & 7;                  // 16B chunk in 128B row
        uint32_t off = (uint32_t)row * 128u + (uint32_t)ch * 16u;
        uint32_t sw  = off ^ ((off >> 3) & 0x70u);
        cp16(sA + sw, A + (size_t)(m0 + row) * K_DIM + k0 + ch * 8);
        cp16(sB + sw, B + (size_t)(n0 + row) * K_DIM + k0 + ch * 8);
    }
    CP_COMMIT();
}

__global__ void __launch_bounds__(256, 2) mxfp4_gemm_kernel(const float* __restrict__ bias,
                                                            float* __restrict__ C) {
    extern __shared__ char smem[];
    const uint32_t sb = smem_u32(smem);
    const int tid  = threadIdx.x;
    const int wid  = tid >> 5;
    const int lane = tid & 31;

    // L2-friendly supertile mapping: groups of 8 mt rows x 32 nt cols (256 CTAs)
    const int group  = blockIdx.x >> 8;
    const int within = blockIdx.x & 255;
    const int mt = group * 8 + (within & 7);
    const int nt = within >> 3;
    const int m0 = mt * 128;
    const int n0 = nt * 128;

    const int wm0 = (wid & 1) * 64;
    const int wn0 = (wid >> 1) * 32;

    if (tid < 128) ((float*)(smem + SMEM_BIAS))[tid] = bias[n0 + tid];

    load_tiles(sb + SMEM_TILES + 0 * STAGE_BYTES, m0, n0, 0 * TK, tid);
    load_tiles(sb + SMEM_TILES + 1 * STAGE_BYTES, m0, n0, 1 * TK, tid);

    float acc[4][4][4];
    #pragma unroll
    for (int i = 0; i < 4; i++)
        #pragma unroll
        for (int j = 0; j < 4; j++)
            #pragma unroll
            for (int r = 0; r < 4; r++) acc[i][j][r] = 0.0f;

    const int aRowL = lane & 15;
    const int aColH = (lane >> 4) & 1;
    const int bRowL = lane & 7;
    const int bSel  = (lane >> 3) & 3;

    for (int kt = 0; kt < KTILES; kt++) {
        const uint32_t cur = sb + SMEM_TILES + (uint32_t)(kt % STAGES) * STAGE_BYTES;
        if (kt == KTILES - 1) { CP_WAIT(0); } else { CP_WAIT(1); }
        __syncthreads();   // tile kt fully resident; slot (kt-1)%3 fully consumed

        // issue next load first: maximal cp.async lead over compute
        if (kt + 2 < KTILES) {
            load_tiles(sb + SMEM_TILES + (uint32_t)((kt + 2) % STAGES) * STAGE_BYTES,
                       m0, n0, (kt + 2) * TK, tid);
        }

        const uint32_t sA = cur;
        const uint32_t sB = cur + 16384u;

        #pragma unroll
        for (int ks = 0; ks < 4; ks++) {
            uint32_t af[4][4];
            #pragma unroll
            for (int mi = 0; mi < 4; mi++) {
                int row  = wm0 + mi * 16 + aRowL;
                int colb = ks * 32 + aColH * 16;
                uint32_t addr = sA + (uint32_t)row * 128u
                              + (uint32_t)(colb ^ ((row & 7) * 16));
                ldmatrix_x4(af[mi][0], af[mi][1], af[mi][2], af[mi][3], addr);
            }
            uint32_t bf[4][2];
            #pragma unroll
            for (int nb = 0; nb < 2; nb++) {
                int nrow = wn0 + (nb * 2 + (bSel >> 1)) * 8 + bRowL;
                int colb = ks * 32 + (bSel & 1) * 16;
                uint32_t addr = sB + (uint32_t)nrow * 128u
                              + (uint32_t)(colb ^ ((nrow & 7) * 16));
                uint32_t r0, r1, r2, r3;
                ldmatrix_x4(r0, r1, r2, r3, addr);
                bf[nb * 2 + 0][0] = r0; bf[nb * 2 + 0][1] = r1;
                bf[nb * 2 + 1][0] = r2; bf[nb * 2 + 1][1] = r3;
            }
            #pragma unroll
            for (int mi = 0; mi < 4; mi++)
                #pragma unroll
                for (int ni = 0; ni < 4; ni++)
                    mma_16816(acc[mi][ni], af[mi], bf[ni]);
        }
    }

    // epilogue: add bias, store
    const float* bsm = (const float*)(smem + SMEM_BIAS);
    const int qr = lane >> 2;
    const int qc = (lane & 3) * 2;
    #pragma unroll
    for (int mi = 0; mi < 4; mi++) {
        #pragma unroll
        for (int ni = 0; ni < 4; ni++) {
            const int col = wn0 + ni * 8 + qc;
            const float b0 = bsm[col], b1 = bsm[col + 1];
            const int r0 = m0 + wm0 + mi * 16 + qr;
            float2 v0 = make_float2(acc[mi][ni][0] + b0, acc[mi][ni][1] + b1);
            float2 v1 = make_float2(acc[mi][ni][2] + b0, acc[mi][ni][3] + b1);
            *reinterpret_cast<float2*>(C + (size_t)r0 * N_DIM + n0 + col) = v0;
            *reinterpret_cast<float2*>(C + (size_t)(r0 + 8) * N_DIM + n0 + col) = v1;
        }
    }
}

// ============================ launch =========================================
extern "C" void kernel_launch(void* const* d_in, const int* in_sizes, int n_in,
                              void* d_out, int out_size) {
    const float* x    = (const float*)d_in[0];
    const float* w    = (const float*)d_in[1];
    const float* bias = (const float*)d_in[2];
    float* out        = (float*)d_out;

    __nv_bfloat16* xq;
    __nv_bfloat16* wq;
    cudaGetSymbolAddress((void**)&xq, g_xq);
    cudaGetSymbolAddress((void**)&wq, g_wq);

    quant_kernel<<<1048576 / 256, 256>>>(x, xq);  // x: 1,048,576 groups
    quant_kernel<<<524288 / 256, 256>>>(w, wq);   // w:   524,288 groups

    cudaFuncSetAttribute(mxfp4_gemm_kernel,
                         cudaFuncAttributeMaxDynamicSharedMemorySize, GEMM_SMEM_BYTES);
    const int grid = (T_DIM / 128) * (N_DIM / 128);  // 2048
    mxfp4_gemm_kernel<<<grid, 256, GEMM_SMEM_BYTES>>>(bias, out);
}